// round 15
// baseline (speedup 1.0000x reference)
#include <cuda_runtime.h>
#include <cstdint>

#define B_ROWS  8192
#define N_DIM   2048
#define KD      64
#define M_TILE  64
#define CHUNK   128
#define NCH     (N_DIM / CHUNK)   // 16
#define THREADS 512
#define SMEM_BYTES 131072
// layout: A buf s at s*32768 (hi [0,16384), lo [16384,32768))
//         B buf s at 65536 + s*32768 (hi [0,16384), lo [16384,32768))
// rows are 256B (128 bf16); swizzle: within each 128B half, 16B chunk index
// is XORed with (row&7).
// barriers: FULL[buf] = id 1+buf (rendezvous, 512); EMPTY[buf] = id 3+buf.

__device__ float g_s[N_DIM];
__device__ unsigned short g_vhi[KD * N_DIM];   // [col][n] bf16 hi (truncated)
__device__ unsigned short g_vlo[KD * N_DIM];   // [col][n] bf16 lo (x - hi, rn)

__device__ __forceinline__ uint32_t pack_hi(float e0, float e1) {
    return __byte_perm(__float_as_uint(e0), __float_as_uint(e1), 0x7632);
}
__device__ __forceinline__ float trunc_hi(float a) {
    return __uint_as_float(__float_as_uint(a) & 0xffff0000u);
}
__device__ __forceinline__ uint32_t pack_lo(float e0, float e1) {
    uint32_t r;
    asm("cvt.rn.bf16x2.f32 %0, %1, %2;" : "=r"(r)
        : "f"(e1 - trunc_hi(e1)), "f"(e0 - trunc_hi(e0)));
    return r;
}

// ---------- prep: transpose v, split bf16 hi/lo, compute s[n] ----------
__global__ void prep_kernel(const float* __restrict__ v) {
    __shared__ float tile[64][65];
    const int t = threadIdx.x;
    const int n0 = blockIdx.x * 64;
#pragma unroll
    for (int kk = 0; kk < 4; kk++) {
        int j = t + kk * 256;
        int r = j >> 4, q = j & 15;
        float4 f = *reinterpret_cast<const float4*>(v + (size_t)(n0 + r) * KD + 4 * q);
        tile[r][4 * q + 0] = f.x; tile[r][4 * q + 1] = f.y;
        tile[r][4 * q + 2] = f.z; tile[r][4 * q + 3] = f.w;
    }
    __syncthreads();
    if (t < 64) {
        float acc = 0.0f;
#pragma unroll 8
        for (int c = 0; c < 64; c++) { float a = tile[t][c]; acc = fmaf(a, a, acc); }
        g_s[n0 + t] = acc;
    }
    const int c = t >> 2, seg = t & 3;
#pragma unroll
    for (int d = 0; d < 16; d += 2) {
        float a0 = tile[seg * 16 + d][c];
        float a1 = tile[seg * 16 + d + 1][c];
        size_t idx = (size_t)c * N_DIM + n0 + seg * 16 + d;
        *reinterpret_cast<uint32_t*>(g_vhi + idx) = pack_hi(a0, a1);
        *reinterpret_cast<uint32_t*>(g_vlo + idx) = pack_lo(a0, a1);
    }
}

// ---------- main kernel ----------
__device__ __forceinline__ uint32_t smem_u32(const void* p) {
    uint32_t a;
    asm("{ .reg .u64 t; cvta.to.shared.u64 t, %1; cvt.u32.u64 %0, t; }"
        : "=r"(a) : "l"(p));
    return a;
}
__device__ __forceinline__ void cpa16(uint32_t dst, const void* src) {
    asm volatile("cp.async.cg.shared.global [%0], [%1], 16;"
                 :: "r"(dst), "l"(src) : "memory");
}
__device__ __forceinline__ void bar_sync(int id) {
    asm volatile("bar.sync %0, 512;" :: "r"(id) : "memory");
}
__device__ __forceinline__ void bar_arrive(int id) {
    asm volatile("bar.arrive %0, 512;" :: "r"(id) : "memory");
}
__device__ __forceinline__ void ldsm4(uint32_t* r, uint32_t a) {
    asm volatile("ldmatrix.sync.aligned.m8n8.x4.shared.b16 {%0,%1,%2,%3}, [%4];"
                 : "=r"(r[0]), "=r"(r[1]), "=r"(r[2]), "=r"(r[3]) : "r"(a));
}
__device__ __forceinline__ void mma_bf16(float* c, const uint32_t* a,
                                         uint32_t b0, uint32_t b1) {
    asm volatile(
        "mma.sync.aligned.m16n8k16.row.col.f32.bf16.bf16.f32 "
        "{%0,%1,%2,%3}, {%4,%5,%6,%7}, {%8,%9}, {%0,%1,%2,%3};"
        : "+f"(c[0]), "+f"(c[1]), "+f"(c[2]), "+f"(c[3])
        : "r"(a[0]), "r"(a[1]), "r"(a[2]), "r"(a[3]), "r"(b0), "r"(b1));
}

// swizzled byte offset within a tile for 16B chunk index c16 of a 256B row
__device__ __forceinline__ uint32_t tile_off(uint32_t row, uint32_t c16) {
    return row * 256u + (c16 >> 3) * 128u + (((c16 & 7u) ^ (row & 7u)) * 16u);
}

__global__ void __launch_bounds__(THREADS)
fm_kernel(const float* __restrict__ x, float* __restrict__ out) {
    extern __shared__ char smem[];
    const uint32_t sb = smem_u32(smem);
    const int t = threadIdx.x;
    const int l = t & 31;
    const int row0 = blockIdx.x * M_TILE;

    // epilogue scratch (regions retired by the time they're used)
    float* red1 = reinterpret_cast<float*>(smem);            // [64][8]  @0
    float* red2 = red1 + 512;                                 // [64][32] @2048
    float* part = reinterpret_cast<float*>(smem + 65536);     // kh=1 acc @B0

    if (t < 256) {
        // ================= PRODUCER (warps 0-7) =================
        const int qi2 = t & 31;          // 4-float k-quad index (0..31)
        const int ri8 = t >> 5;          // row-in-8 (0..7); rows 8i+ri8
        const int pcol = t >> 2, pk = t & 3;   // B staging: col, k16 base

        float t2acc[8] = {0.f,0.f,0.f,0.f,0.f,0.f,0.f,0.f};
        float4 px[8];

        // issue B(0)
#pragma unroll
        for (int p = 0; p < 4; p++) {
            int k16 = pk + p * 4;
            uint32_t d = sb + 65536u + tile_off((uint32_t)pcol, (uint32_t)k16);
            size_t srcoff = (size_t)pcol * N_DIM + k16 * 8;
            cpa16(d, g_vhi + srcoff);
            cpa16(d + 16384u, g_vlo + srcoff);
        }
        asm volatile("cp.async.commit_group;" ::: "memory");

        // load x chunk 0
#pragma unroll
        for (int i = 0; i < 8; i++)
            px[i] = *reinterpret_cast<const float4*>(
                x + (size_t)(row0 + 8 * i + ri8) * N_DIM + 4 * qi2);

        for (int c = 0; c < NCH; c++) {
            const int buf = c & 1;
            if (c >= 2) bar_sync(3 + buf);          // EMPTY[buf]

            // convert px(c) -> A[buf]; t2
            char* Ab = smem + buf * 32768;
            float4 s4 = *reinterpret_cast<const float4*>(g_s + c * CHUNK + 4 * qi2);
#pragma unroll
            for (int i = 0; i < 8; i++) {
                float4 f = px[i];
                t2acc[i] = fmaf(f.x * f.x, s4.x, t2acc[i]);
                t2acc[i] = fmaf(f.y * f.y, s4.y, t2acc[i]);
                t2acc[i] = fmaf(f.z * f.z, s4.z, t2acc[i]);
                t2acc[i] = fmaf(f.w * f.w, s4.w, t2acc[i]);
                uint32_t row = (uint32_t)(8 * i + ri8);
                uint32_t off = tile_off(row, (uint32_t)(qi2 >> 1))
                             + (uint32_t)((qi2 & 1) * 8);
                *reinterpret_cast<uint2*>(Ab + off) =
                    make_uint2(pack_hi(f.x, f.y), pack_hi(f.z, f.w));
                *reinterpret_cast<uint2*>(Ab + 16384 + off) =
                    make_uint2(pack_lo(f.x, f.y), pack_lo(f.z, f.w));
            }

            // prefetch x chunk c+1 (clamped)
            {
                int cn = (c + 1 < NCH) ? c + 1 : NCH - 1;
#pragma unroll
                for (int i = 0; i < 8; i++)
                    px[i] = *reinterpret_cast<const float4*>(
                        x + (size_t)(row0 + 8 * i + ri8) * N_DIM
                          + cn * CHUNK + 4 * qi2);
            }

            // B(c) must be resident before handoff
            asm volatile("cp.async.wait_group 0;" ::: "memory");
            bar_sync(1 + buf);                      // FULL[buf] rendezvous

            // issue B(c+1) — safe: rendezvous proved consumer done with c-1
            if (c + 1 < NCH) {
                const uint32_t bbase = sb + 65536u + (uint32_t)(buf ^ 1) * 32768u;
#pragma unroll
                for (int p = 0; p < 4; p++) {
                    int k16 = pk + p * 4;
                    uint32_t d = bbase + tile_off((uint32_t)pcol, (uint32_t)k16);
                    size_t srcoff = (size_t)pcol * N_DIM + (c + 1) * CHUNK + k16 * 8;
                    cpa16(d, g_vhi + srcoff);
                    cpa16(d + 16384u, g_vlo + srcoff);
                }
                asm volatile("cp.async.commit_group;" ::: "memory");
            }
        }

        // t2 partials -> red2 (A0 region; consumers done with A0 per FULL(15))
#pragma unroll
        for (int i = 0; i < 8; i++)
            red2[(8 * i + ri8) * 32 + qi2] = t2acc[i];

    } else {
        // ================= CONSUMER (warps 8-15) =================
        const int w2 = (t >> 5) - 8;
        const int mw = w2 & 1, nh = (w2 >> 1) & 1, kh = w2 >> 2;
        const uint32_t a_ksel = (uint32_t)((l >> 4) & 1);
        const uint32_t b_rowb = (uint32_t)((l & 7) + ((l >> 4) & 1) * 8 + 32 * nh);
        const uint32_t b_ksel = (uint32_t)((l >> 3) & 1);

        float acc[2][4][4];
#pragma unroll
        for (int mg = 0; mg < 2; mg++)
#pragma unroll
            for (int i = 0; i < 4; i++)
#pragma unroll
                for (int j = 0; j < 4; j++) acc[mg][i][j] = 0.0f;

        for (int c = 0; c < NCH; c++) {
            const int buf = c & 1;
            const uint32_t Ab = sb + (uint32_t)buf * 32768u;
            const uint32_t Bb = sb + 65536u + (uint32_t)buf * 32768u;

            bar_sync(1 + buf);                      // FULL[buf] rendezvous

#pragma unroll
            for (int kk = 0; kk < 4; kk++) {
                const uint32_t kc = (uint32_t)(4 * kh + kk);
                uint32_t ah[2][4], al[2][4], bh[2][4], bl[2][4];
#pragma unroll
                for (int mg = 0; mg < 2; mg++) {
                    uint32_t arow = (uint32_t)((l & 7) + ((l >> 3) & 1) * 8
                                               + 16 * (2 * mw + mg));
                    uint32_t addrA = tile_off(arow, 2u * kc + a_ksel);
                    ldsm4(ah[mg], Ab + addrA);
                    ldsm4(al[mg], Ab + 16384u + addrA);
                }
#pragma unroll
                for (int tp = 0; tp < 2; tp++) {
                    uint32_t brow = b_rowb + 16u * tp;
                    uint32_t addrB = tile_off(brow, 2u * kc + b_ksel);
                    ldsm4(bh[tp], Bb + addrB);
                    ldsm4(bl[tp], Bb + 16384u + addrB);
                }
                // phase 1: hi*hi — 8 independent accumulator quartets
#pragma unroll
                for (int tp = 0; tp < 2; tp++)
#pragma unroll
                    for (int mg = 0; mg < 2; mg++) {
                        mma_bf16(acc[mg][2 * tp],     ah[mg], bh[tp][0], bh[tp][1]);
                        mma_bf16(acc[mg][2 * tp + 1], ah[mg], bh[tp][2], bh[tp][3]);
                    }
                // phase 2: lo*hi — same accs, reuse distance 8
#pragma unroll
                for (int tp = 0; tp < 2; tp++)
#pragma unroll
                    for (int mg = 0; mg < 2; mg++) {
                        mma_bf16(acc[mg][2 * tp],     al[mg], bh[tp][0], bh[tp][1]);
                        mma_bf16(acc[mg][2 * tp + 1], al[mg], bh[tp][2], bh[tp][3]);
                    }
                // phase 3: hi*lo
#pragma unroll
                for (int tp = 0; tp < 2; tp++)
#pragma unroll
                    for (int mg = 0; mg < 2; mg++) {
                        mma_bf16(acc[mg][2 * tp],     ah[mg], bl[tp][0], bl[tp][1]);
                        mma_bf16(acc[mg][2 * tp + 1], ah[mg], bl[tp][2], bl[tp][3]);
                    }
            }

            bar_arrive(3 + buf);                    // EMPTY[buf]
        }

        // kh=1: spill k-partials to part buffer (B0 region, retired)
        const int pbase = (((mw * 2 + nh) * 32) + l) * 32;
        if (kh == 1) {
#pragma unroll
            for (int mg = 0; mg < 2; mg++)
#pragma unroll
                for (int tl = 0; tl < 4; tl++)
#pragma unroll
                    for (int j = 0; j < 4; j++)
                        part[pbase + (mg * 4 + tl) * 4 + j] = acc[mg][tl][j];
        }

        __syncthreads();   // converge with producers (they hit the one below)

        if (kh == 0) {
#pragma unroll
            for (int mg = 0; mg < 2; mg++) {
                float s_lo = 0.0f, s_hi = 0.0f;
#pragma unroll
                for (int tl = 0; tl < 4; tl++) {
#pragma unroll
                    for (int j = 0; j < 4; j++) {
                        int idx = pbase + (mg * 4 + tl) * 4 + j;
                        float v = acc[mg][tl][j] + part[idx];
                        // c0,c1 -> row (l>>2); c2,c3 -> row (l>>2)+8
                        if (j < 2) s_lo = fmaf(v, v, s_lo);
                        else       s_hi = fmaf(v, v, s_hi);
                    }
                }
                int r = 16 * (2 * mw + mg) + (l >> 2);
                int cc = nh * 4 + (l & 3);
                red1[r * 8 + cc] = s_lo;
                red1[(r + 8) * 8 + cc] = s_hi;
            }
        }
    }

    if (t < 256) __syncthreads();   // producers' matching arrival
    __syncthreads();                // all: red1/red2 complete

    if (t < M_TILE) {
        float s1 = 0.0f;
#pragma unroll
        for (int q = 0; q < 8; q++) s1 += red1[t * 8 + q];
        float s2 = 0.0f;
#pragma unroll
        for (int q = 0; q < 32; q++) s2 += red2[t * 32 + q];
        out[row0 + t] = 0.5f * (s1 - s2);
    }
}

extern "C" void kernel_launch(void* const* d_in, const int* in_sizes, int n_in,
                              void* d_out, int out_size) {
    const float* x = (const float*)d_in[0];   // [8192, 2048] fp32
    const float* v = (const float*)d_in[1];   // [2048, 64]   fp32
    float* out = (float*)d_out;               // [8192, 1]    fp32

    static bool attr_set = false;
    if (!attr_set) {
        cudaFuncSetAttribute(fm_kernel,
                             cudaFuncAttributeMaxDynamicSharedMemorySize, SMEM_BYTES);
        attr_set = true;
    }
    prep_kernel<<<N_DIM / 64, 256>>>(v);
    fm_kernel<<<B_ROWS / M_TILE, THREADS, SMEM_BYTES>>>(x, out);
}

// round 16
// speedup vs baseline: 1.4431x; 1.4431x over previous
#include <cuda_runtime.h>
#include <cstdint>
#include <cuda_fp16.h>

#define B_ROWS  8192
#define N_DIM   2048
#define KD      64
#define M_TILE  64
#define CHUNK   128
#define NCH     (N_DIM / CHUNK)   // 16
#define THREADS 512
#define SMEM_BYTES 65536
// layout: A buf s at s*16384 (fp16, 64 rows x 256B)
//         B buf s at 32768 + s*16384
// rows are 256B (128 fp16); swizzle: within each 128B half, 16B chunk index
// is XORed with (row&7).
// barriers: FULL[buf] = id 1+buf (rendezvous, 512); EMPTY[buf] = id 3+buf.

__device__ float g_s[N_DIM];
__device__ unsigned short g_vf16[KD * N_DIM];   // [col][n] fp16 (rn)

__device__ __forceinline__ uint32_t pack_f16(float e0, float e1) {
    uint32_t r;
    asm("cvt.rn.f16x2.f32 %0, %1, %2;" : "=r"(r) : "f"(e1), "f"(e0));
    return r;
}

// ---------- prep: transpose v, fp16-rn, compute s[n] ----------
__global__ void prep_kernel(const float* __restrict__ v) {
    __shared__ float tile[64][65];
    const int t = threadIdx.x;
    const int n0 = blockIdx.x * 64;
#pragma unroll
    for (int kk = 0; kk < 4; kk++) {
        int j = t + kk * 256;
        int r = j >> 4, q = j & 15;
        float4 f = *reinterpret_cast<const float4*>(v + (size_t)(n0 + r) * KD + 4 * q);
        tile[r][4 * q + 0] = f.x; tile[r][4 * q + 1] = f.y;
        tile[r][4 * q + 2] = f.z; tile[r][4 * q + 3] = f.w;
    }
    __syncthreads();
    if (t < 64) {
        float acc = 0.0f;
#pragma unroll 8
        for (int c = 0; c < 64; c++) { float a = tile[t][c]; acc = fmaf(a, a, acc); }
        g_s[n0 + t] = acc;
    }
    const int c = t >> 2, seg = t & 3;
#pragma unroll
    for (int d = 0; d < 16; d += 2) {
        float a0 = tile[seg * 16 + d][c];
        float a1 = tile[seg * 16 + d + 1][c];
        size_t idx = (size_t)c * N_DIM + n0 + seg * 16 + d;
        *reinterpret_cast<uint32_t*>(g_vf16 + idx) = pack_f16(a0, a1);
    }
}

// ---------- main kernel ----------
__device__ __forceinline__ uint32_t smem_u32(const void* p) {
    uint32_t a;
    asm("{ .reg .u64 t; cvta.to.shared.u64 t, %1; cvt.u32.u64 %0, t; }"
        : "=r"(a) : "l"(p));
    return a;
}
__device__ __forceinline__ void cpa16(uint32_t dst, const void* src) {
    asm volatile("cp.async.cg.shared.global [%0], [%1], 16;"
                 :: "r"(dst), "l"(src) : "memory");
}
__device__ __forceinline__ void bar_sync(int id) {
    asm volatile("bar.sync %0, 512;" :: "r"(id) : "memory");
}
__device__ __forceinline__ void bar_arrive(int id) {
    asm volatile("bar.arrive %0, 512;" :: "r"(id) : "memory");
}
__device__ __forceinline__ void ldsm4(uint32_t* r, uint32_t a) {
    asm volatile("ldmatrix.sync.aligned.m8n8.x4.shared.b16 {%0,%1,%2,%3}, [%4];"
                 : "=r"(r[0]), "=r"(r[1]), "=r"(r[2]), "=r"(r[3]) : "r"(a));
}
__device__ __forceinline__ void mma_f16(float* c, const uint32_t* a,
                                        uint32_t b0, uint32_t b1) {
    asm volatile(
        "mma.sync.aligned.m16n8k16.row.col.f32.f16.f16.f32 "
        "{%0,%1,%2,%3}, {%4,%5,%6,%7}, {%8,%9}, {%0,%1,%2,%3};"
        : "+f"(c[0]), "+f"(c[1]), "+f"(c[2]), "+f"(c[3])
        : "r"(a[0]), "r"(a[1]), "r"(a[2]), "r"(a[3]), "r"(b0), "r"(b1));
}

// swizzled byte offset within a tile for 16B chunk index c16 of a 256B row
__device__ __forceinline__ uint32_t tile_off(uint32_t row, uint32_t c16) {
    return row * 256u + (c16 >> 3) * 128u + (((c16 & 7u) ^ (row & 7u)) * 16u);
}

__global__ void __launch_bounds__(THREADS)
fm_kernel(const float* __restrict__ x, float* __restrict__ out) {
    extern __shared__ char smem[];
    const uint32_t sb = smem_u32(smem);
    const int t = threadIdx.x;
    const int l = t & 31;
    const int row0 = blockIdx.x * M_TILE;

    // epilogue scratch (regions retired by the time they're used)
    float* red1 = reinterpret_cast<float*>(smem);            // [64][8]  @0
    float* red2 = red1 + 512;                                 // [64][32] @2048
    float* part = reinterpret_cast<float*>(smem + 32768);     // kh=1 acc @B0

    if (t < 256) {
        // ================= PRODUCER (warps 0-7) =================
        const int qi2 = t & 31;          // 4-float k-quad index (0..31)
        const int ri8 = t >> 5;          // row-in-8 (0..7); rows 8i+ri8
        const int pcol = t >> 2, pk = t & 3;   // B staging: col, k16 base

        float t2acc[8] = {0.f,0.f,0.f,0.f,0.f,0.f,0.f,0.f};
        float4 px[8];

        // issue B(0)
#pragma unroll
        for (int p = 0; p < 4; p++) {
            int k16 = pk + p * 4;
            uint32_t d = sb + 32768u + tile_off((uint32_t)pcol, (uint32_t)k16);
            cpa16(d, g_vf16 + (size_t)pcol * N_DIM + k16 * 8);
        }
        asm volatile("cp.async.commit_group;" ::: "memory");

        // load x chunk 0
#pragma unroll
        for (int i = 0; i < 8; i++)
            px[i] = *reinterpret_cast<const float4*>(
                x + (size_t)(row0 + 8 * i + ri8) * N_DIM + 4 * qi2);

        for (int c = 0; c < NCH; c++) {
            const int buf = c & 1;
            if (c >= 2) bar_sync(3 + buf);          // EMPTY[buf]

            // convert px(c) -> A[buf] fp16; t2
            char* Ab = smem + buf * 16384;
            float4 s4 = *reinterpret_cast<const float4*>(g_s + c * CHUNK + 4 * qi2);
#pragma unroll
            for (int i = 0; i < 8; i++) {
                float4 f = px[i];
                t2acc[i] = fmaf(f.x * f.x, s4.x, t2acc[i]);
                t2acc[i] = fmaf(f.y * f.y, s4.y, t2acc[i]);
                t2acc[i] = fmaf(f.z * f.z, s4.z, t2acc[i]);
                t2acc[i] = fmaf(f.w * f.w, s4.w, t2acc[i]);
                uint32_t row = (uint32_t)(8 * i + ri8);
                uint32_t off = tile_off(row, (uint32_t)(qi2 >> 1))
                             + (uint32_t)((qi2 & 1) * 8);
                *reinterpret_cast<uint2*>(Ab + off) =
                    make_uint2(pack_f16(f.x, f.y), pack_f16(f.z, f.w));
            }

            // prefetch x chunk c+1 (clamped)
            {
                int cn = (c + 1 < NCH) ? c + 1 : NCH - 1;
#pragma unroll
                for (int i = 0; i < 8; i++)
                    px[i] = *reinterpret_cast<const float4*>(
                        x + (size_t)(row0 + 8 * i + ri8) * N_DIM
                          + cn * CHUNK + 4 * qi2);
            }

            // B(c) must be resident before handoff
            asm volatile("cp.async.wait_group 0;" ::: "memory");
            bar_sync(1 + buf);                      // FULL[buf] rendezvous

            // issue B(c+1) — safe: rendezvous proved consumer done with c-1
            if (c + 1 < NCH) {
                const uint32_t bbase = sb + 32768u + (uint32_t)(buf ^ 1) * 16384u;
#pragma unroll
                for (int p = 0; p < 4; p++) {
                    int k16 = pk + p * 4;
                    uint32_t d = bbase + tile_off((uint32_t)pcol, (uint32_t)k16);
                    cpa16(d, g_vf16 + (size_t)pcol * N_DIM
                                    + (c + 1) * CHUNK + k16 * 8);
                }
                asm volatile("cp.async.commit_group;" ::: "memory");
            }
        }

        // t2 partials -> red2 (A0 region; consumers done with A0 per FULL(15))
#pragma unroll
        for (int i = 0; i < 8; i++)
            red2[(8 * i + ri8) * 32 + qi2] = t2acc[i];

    } else {
        // ================= CONSUMER (warps 8-15) =================
        const int w2 = (t >> 5) - 8;
        const int mw = w2 & 1, nh = (w2 >> 1) & 1, kh = w2 >> 2;
        const uint32_t a_ksel = (uint32_t)((l >> 4) & 1);
        const uint32_t b_rowb = (uint32_t)((l & 7) + ((l >> 4) & 1) * 8 + 32 * nh);
        const uint32_t b_ksel = (uint32_t)((l >> 3) & 1);

        float acc[2][4][4];
#pragma unroll
        for (int mg = 0; mg < 2; mg++)
#pragma unroll
            for (int i = 0; i < 4; i++)
#pragma unroll
                for (int j = 0; j < 4; j++) acc[mg][i][j] = 0.0f;

        for (int c = 0; c < NCH; c++) {
            const int buf = c & 1;
            const uint32_t Ab = sb + (uint32_t)buf * 16384u;
            const uint32_t Bb = sb + 32768u + (uint32_t)buf * 16384u;

            bar_sync(1 + buf);                      // FULL[buf] rendezvous

#pragma unroll
            for (int kk = 0; kk < 4; kk++) {
                const uint32_t kc = (uint32_t)(4 * kh + kk);
                uint32_t af[2][4], bf[2][4];
#pragma unroll
                for (int mg = 0; mg < 2; mg++) {
                    uint32_t arow = (uint32_t)((l & 7) + ((l >> 3) & 1) * 8
                                               + 16 * (2 * mw + mg));
                    ldsm4(af[mg], Ab + tile_off(arow, 2u * kc + a_ksel));
                }
#pragma unroll
                for (int tp = 0; tp < 2; tp++) {
                    uint32_t brow = b_rowb + 16u * tp;
                    ldsm4(bf[tp], Bb + tile_off(brow, 2u * kc + b_ksel));
                }
#pragma unroll
                for (int tp = 0; tp < 2; tp++)
#pragma unroll
                    for (int mg = 0; mg < 2; mg++) {
                        mma_f16(acc[mg][2 * tp],     af[mg], bf[tp][0], bf[tp][1]);
                        mma_f16(acc[mg][2 * tp + 1], af[mg], bf[tp][2], bf[tp][3]);
                    }
            }

            bar_arrive(3 + buf);                    // EMPTY[buf]
        }

        // kh=1: spill k-partials to part buffer (B0 region, retired)
        const int pbase = (((mw * 2 + nh) * 32) + l) * 32;
        if (kh == 1) {
#pragma unroll
            for (int mg = 0; mg < 2; mg++)
#pragma unroll
                for (int tl = 0; tl < 4; tl++)
#pragma unroll
                    for (int j = 0; j < 4; j++)
                        part[pbase + (mg * 4 + tl) * 4 + j] = acc[mg][tl][j];
        }

        __syncthreads();   // converge with producers (they hit the one below)

        if (kh == 0) {
#pragma unroll
            for (int mg = 0; mg < 2; mg++) {
                float s_lo = 0.0f, s_hi = 0.0f;
#pragma unroll
                for (int tl = 0; tl < 4; tl++) {
#pragma unroll
                    for (int j = 0; j < 4; j++) {
                        int idx = pbase + (mg * 4 + tl) * 4 + j;
                        float v = acc[mg][tl][j] + part[idx];
                        // c0,c1 -> row (l>>2); c2,c3 -> row (l>>2)+8
                        if (j < 2) s_lo = fmaf(v, v, s_lo);
                        else       s_hi = fmaf(v, v, s_hi);
                    }
                }
                int r = 16 * (2 * mw + mg) + (l >> 2);
                int cc = nh * 4 + (l & 3);
                red1[r * 8 + cc] = s_lo;
                red1[(r + 8) * 8 + cc] = s_hi;
            }
        }
    }

    if (t < 256) __syncthreads();   // producers' matching arrival
    __syncthreads();                // all: red1/red2 complete

    if (t < M_TILE) {
        float s1 = 0.0f;
#pragma unroll
        for (int q = 0; q < 8; q++) s1 += red1[t * 8 + q];
        float s2 = 0.0f;
#pragma unroll
        for (int q = 0; q < 32; q++) s2 += red2[t * 32 + q];
        out[row0 + t] = 0.5f * (s1 - s2);
    }
}

extern "C" void kernel_launch(void* const* d_in, const int* in_sizes, int n_in,
                              void* d_out, int out_size) {
    const float* x = (const float*)d_in[0];   // [8192, 2048] fp32
    const float* v = (const float*)d_in[1];   // [2048, 64]   fp32
    float* out = (float*)d_out;               // [8192, 1]    fp32

    static bool attr_set = false;
    if (!attr_set) {
        cudaFuncSetAttribute(fm_kernel,
                             cudaFuncAttributeMaxDynamicSharedMemorySize, SMEM_BYTES);
        attr_set = true;
    }
    prep_kernel<<<N_DIM / 64, 256>>>(v);
    fm_kernel<<<B_ROWS / M_TILE, THREADS, SMEM_BYTES>>>(x, out);
}